// round 9
// baseline (speedup 1.0000x reference)
#include <cuda_runtime.h>
#include <cstdint>

// CRF forward scan. 128-thread blocks = TWO independent 64-thread "pair
// engines" (warps 0-1 -> batch 2b, warps 2-3 -> batch 2b+1), so warps spread
// over all 4 SMSPs (wid%4). Pair engines sync only via named barriers.
// Per pair: thread tid64=32*w2+lane owns state tid64. Each thread computes
// partial sums over its own warp's v-half for columns lane and lane+32;
// keeps one, publishes one float. alpha base-2 scaled; ex2/lg2 approx PTX.
// m = stale-by-2 pair max. feats/masks staged via cp.async 3-buffer pipeline.

#define TT 64
#define CHUNK 16
#define L2E 1.4426950408889634f
#define LN2 0.6931471805599453f
typedef unsigned long long u64;

__device__ float g_Wt[TT * TT];  // g_Wt[j*64+i] = exp(trans[i][j]-c_j)
__device__ float g_c2[TT];       // c_j * log2(e)

__device__ __forceinline__ u64 pack2(float lo, float hi) {
    u64 r; asm("mov.b64 %0, {%1, %2};" : "=l"(r) : "f"(lo), "f"(hi)); return r;
}
__device__ __forceinline__ void unpack2(u64 v, float& lo, float& hi) {
    asm("mov.b64 {%0, %1}, %2;" : "=f"(lo), "=f"(hi) : "l"(v));
}
__device__ __forceinline__ u64 ffma2(u64 a, u64 b, u64 c) {
    u64 d; asm("fma.rn.f32x2 %0, %1, %2, %3;" : "=l"(d) : "l"(a), "l"(b), "l"(c)); return d;
}
__device__ __forceinline__ u64 fadd2(u64 a, u64 b) {
    u64 d; asm("add.rn.f32x2 %0, %1, %2;" : "=l"(d) : "l"(a), "l"(b)); return d;
}
__device__ __forceinline__ float ex2f(float x) {
    float y; asm("ex2.approx.f32 %0, %1;" : "=f"(y) : "f"(x)); return y;
}
__device__ __forceinline__ float lg2f(float x) {
    float y; asm("lg2.approx.f32 %0, %1;" : "=f"(y) : "f"(x)); return y;
}
__device__ __forceinline__ uint32_t smem_u32(const void* p) {
    uint32_t a;
    asm("{ .reg .u64 t; cvta.to.shared.u64 t, %1; cvt.u32.u64 %0, t; }" : "=r"(a) : "l"(p));
    return a;
}
__device__ __forceinline__ int fkey(float x) {
    int b = __float_as_int(x);
    return b >= 0 ? b : (b ^ 0x7fffffff);
}
__device__ __forceinline__ float funkey(int k) {
    return __int_as_float(k >= 0 ? k : (k ^ 0x7fffffff));
}

// ---------------------------------------------------------------------------
__global__ void crf_prep_kernel(const float* __restrict__ trans) {
    int j = threadIdx.x;
    float c = -3.402823466e+38f;
    #pragma unroll
    for (int i = 0; i < TT; i++) c = fmaxf(c, trans[i * TT + j]);
    g_c2[j] = c * L2E;
    #pragma unroll
    for (int i = 0; i < TT; i++) g_Wt[j * TT + i] = __expf(trans[i * TT + j] - c);
}

// ---------------------------------------------------------------------------
__global__ void __launch_bounds__(128) crf_scan_kernel(
    const float* __restrict__ feats,   // [B, S, 64]
    const float* __restrict__ masks,   // [B, S]
    float* __restrict__ out,           // [B, 64]
    int Sdim)
{
    const int warp  = threadIdx.x >> 5;      // 0..3  -> SMSP 0..3
    const int lane  = threadIdx.x & 31;
    const int pair  = warp >> 1;              // 0: batch 2b, 1: batch 2b+1
    const int w2    = warp & 1;               // warp-within-pair
    const int tid64 = w2 * 32 + lane;         // owned state 0..63
    const int b     = blockIdx.x * 2 + pair;
    const int barid = pair + 1;               // named barrier per pair

    __shared__ float s_feat[2][3][CHUNK][TT];  // 24 KB (per-pair staged feats)
    __shared__ float s_mask[2][3][CHUNK];
    __shared__ float s_v[2][TT];               // per-pair v (warp-private halves)
    __shared__ float s_part[2][2][TT];         // per-pair cross-warp partials
    __shared__ float s_wm[2][4][2];            // per-pair stale-max ring

    // W for columns (lane, lane+32), OWN rows [32*w2, 32*w2+32).
    u64 wA[16], wB[16];
    {
        const float4* pa = reinterpret_cast<const float4*>(&g_Wt[lane * TT + 32 * w2]);
        const float4* pb = reinterpret_cast<const float4*>(&g_Wt[(lane + 32) * TT + 32 * w2]);
        #pragma unroll
        for (int q = 0; q < 8; q++) {
            float4 fa = pa[q];
            wA[2 * q]     = pack2(fa.x, fa.y);
            wA[2 * q + 1] = pack2(fa.z, fa.w);
            float4 fb = pb[q];
            wB[2 * q]     = pack2(fb.x, fb.y);
            wB[2 * q + 1] = pack2(fb.z, fb.w);
        }
    }
    const float cj2 = g_c2[tid64];

    const float* fbp = feats + (size_t)b * Sdim * TT;
    const float* mbp = masks + (size_t)b * Sdim;
    const uint32_t feat_s0 = smem_u32(&s_feat[pair][0][0][0]);
    const uint32_t mask_s0 = smem_u32(&s_mask[pair][0][0]);

    const int NC = (Sdim + CHUNK - 1) / CHUNK;

    // Stage chunk c into the pair's buffer c%3 — fully async.
    auto stage = [&](int c) {
        const int base = c * CHUNK;
        const int bufo = (c % 3) * CHUNK * TT;
        #pragma unroll
        for (int q = 0; q < 4; q++) {
            int g   = q * 64 + tid64;      // 16B granule 0..255
            int row = g >> 4;
            int col = (g & 15) << 2;
            int gr  = base + row; if (gr >= Sdim) gr = Sdim - 1;
            const float* src = fbp + (size_t)gr * TT + col;
            uint32_t dst = feat_s0 + (uint32_t)(bufo + row * TT + col) * 4u;
            asm volatile("cp.async.cg.shared.global [%0], [%1], 16;" :: "r"(dst), "l"(src));
        }
        if (tid64 < CHUNK) {
            int gr = base + tid64; if (gr >= Sdim) gr = Sdim - 1;
            const float* src = mbp + gr;
            uint32_t dst = mask_s0 + (uint32_t)((c % 3) * CHUNK + tid64) * 4u;
            asm volatile("cp.async.ca.shared.global [%0], [%1], 4;" :: "r"(dst), "l"(src));
        }
    };

    stage(0);
    asm volatile("cp.async.commit_group;");
    if (NC > 1) stage(1);
    asm volatile("cp.async.commit_group;");
    asm volatile("cp.async.wait_group 1;");
    asm volatile("bar.sync %0, 64;" :: "r"(barid) : "memory");

    float alpha = s_feat[pair][0][0][tid64] * L2E;   // base-2 scaled alpha0

    // Exact initial shift; seed ring slot 1.
    {
        float wmx = funkey(__reduce_max_sync(0xffffffffu, fkey(alpha)));
        if (lane == 0) s_wm[pair][1][w2] = wmx;
    }
    asm volatile("bar.sync %0, 64;" :: "r"(barid) : "memory");
    float m = fmaxf(s_wm[pair][1][0], s_wm[pair][1][1]);

    for (int c = 0; c < NC; c++) {
        if (c > 0) asm volatile("cp.async.wait_group 1;");
        if (c + 2 < NC) stage(c + 2);
        asm volatile("cp.async.commit_group;");
        asm volatile("bar.sync %0, 64;" :: "r"(barid) : "memory");

        #pragma unroll
        for (int r = 0; r < CHUNK; r++) {
            const int t = c * CHUNK + r;
            if (t >= 1 && t < Sdim) {
                // Chain head: exp2 with stale shift, publish own v.
                const float v = ex2f(alpha - m);
                s_v[pair][tid64] = v;

                // Off-chain: staged feat/mask, blend precompute, stale max.
                const float ft  = s_feat[pair][c % 3][r][tid64] * L2E;
                const float mk  = s_mask[pair][c % 3][r];
                const float pre = ft + cj2 + m;
                const float t0  = pre * mk + alpha * (1.0f - mk);
                const float mnext = fmaxf(s_wm[pair][r & 3][0], s_wm[pair][r & 3][1]);
                {
                    float wmx = funkey(__reduce_max_sync(0xffffffffu, fkey(alpha)));
                    if (lane == 0) s_wm[pair][(r + 1) & 3][w2] = wmx;
                }

                __syncwarp();

                // Own-half matvec for columns lane and lane+32.
                const float4* vp = reinterpret_cast<const float4*>(&s_v[pair][32 * w2]);
                u64 accA[4] = {0ull, 0ull, 0ull, 0ull};
                u64 accB[4] = {0ull, 0ull, 0ull, 0ull};
                #pragma unroll
                for (int q = 0; q < 8; q++) {
                    float4 f = vp[q];
                    u64 v01 = pack2(f.x, f.y);
                    u64 v23 = pack2(f.z, f.w);
                    accA[(2 * q) & 3]     = ffma2(v01, wA[2 * q],     accA[(2 * q) & 3]);
                    accA[(2 * q + 1) & 3] = ffma2(v23, wA[2 * q + 1], accA[(2 * q + 1) & 3]);
                    accB[(2 * q) & 3]     = ffma2(v01, wB[2 * q],     accB[(2 * q) & 3]);
                    accB[(2 * q + 1) & 3] = ffma2(v23, wB[2 * q + 1], accB[(2 * q + 1) & 3]);
                }
                u64 sA = fadd2(fadd2(accA[0], accA[1]), fadd2(accA[2], accA[3]));
                u64 sB = fadd2(fadd2(accB[0], accB[1]), fadd2(accB[2], accB[3]));
                float al, ah, bl, bh;
                unpack2(sA, al, ah);
                unpack2(sB, bl, bh);
                const float PA = al + ah;               // partial, column lane
                const float PB = bl + bh;               // partial, column lane+32

                // Keep the owned state's partial; publish the other.
                const float keep = (w2 == 0) ? PA : PB;
                const float pub  = (w2 == 0) ? PB : PA;
                s_part[pair][r & 1][tid64 ^ 32] = pub;

                asm volatile("bar.sync %0, 64;" :: "r"(barid) : "memory");

                // Tail: combine halves, log2, blend.
                const float P = keep + s_part[pair][r & 1][tid64];
                alpha = fmaf(lg2f(P), mk, t0);
                m = mnext;
            }
        }
    }

    out[(size_t)b * TT + tid64] = alpha * LN2;
}

// ---------------------------------------------------------------------------
extern "C" void kernel_launch(void* const* d_in, const int* in_sizes, int n_in,
                              void* d_out, int out_size) {
    const float* feats = (const float*)d_in[0];
    const float* masks = (const float*)d_in[1];
    const float* trans = (const float*)d_in[2];
    float* out = (float*)d_out;

    const int Bn   = out_size / TT;
    const int Sdim = in_sizes[0] / (Bn * TT);

    crf_prep_kernel<<<1, TT>>>(trans);
    crf_scan_kernel<<<Bn / 2, 128>>>(feats, masks, out, Sdim);
}

// round 10
// speedup vs baseline: 1.1419x; 1.1419x over previous
#include <cuda_runtime.h>
#include <cstdint>

// CRF forward scan, 512 blocks x 64 threads. Thread tid=32*w2+lane owns state
// tid. Per step each thread computes partial sums over its own warp's v-half
// (rows [32*w2,32*w2+32)) for columns tid (kept) and tid^32 (published, 1 float).
// Shift m = stale-by-1 alpha[state 1] (block-uniform, LSE shift-invariant;
// cross-state alpha spread << fp32 exp2 range). alpha kept base-2 scaled;
// ex2/lg2 approx PTX. feats/masks staged via cp.async 3-buffer pipeline.

#define TT 64
#define CHUNK 16
#define L2E 1.4426950408889634f
#define LN2 0.6931471805599453f
typedef unsigned long long u64;

__device__ float g_Wt[TT * TT];  // g_Wt[j*64+i] = exp(trans[i][j]-c_j)
__device__ float g_c2[TT];       // c_j * log2(e)

__device__ __forceinline__ void unpack2(u64 v, float& lo, float& hi) {
    asm("mov.b64 {%0, %1}, %2;" : "=f"(lo), "=f"(hi) : "l"(v));
}
__device__ __forceinline__ u64 ffma2(u64 a, u64 b, u64 c) {
    u64 d; asm("fma.rn.f32x2 %0, %1, %2, %3;" : "=l"(d) : "l"(a), "l"(b), "l"(c)); return d;
}
__device__ __forceinline__ u64 fadd2(u64 a, u64 b) {
    u64 d; asm("add.rn.f32x2 %0, %1, %2;" : "=l"(d) : "l"(a), "l"(b)); return d;
}
__device__ __forceinline__ float ex2f(float x) {
    float y; asm("ex2.approx.f32 %0, %1;" : "=f"(y) : "f"(x)); return y;
}
__device__ __forceinline__ float lg2f(float x) {
    float y; asm("lg2.approx.f32 %0, %1;" : "=f"(y) : "f"(x)); return y;
}
__device__ __forceinline__ uint32_t smem_u32(const void* p) {
    uint32_t a;
    asm("{ .reg .u64 t; cvta.to.shared.u64 t, %1; cvt.u32.u64 %0, t; }" : "=r"(a) : "l"(p));
    return a;
}

// ---------------------------------------------------------------------------
__global__ void crf_prep_kernel(const float* __restrict__ trans) {
    int j = threadIdx.x;
    float c = -3.402823466e+38f;
    #pragma unroll
    for (int i = 0; i < TT; i++) c = fmaxf(c, trans[i * TT + j]);
    g_c2[j] = c * L2E;
    #pragma unroll
    for (int i = 0; i < TT; i++) g_Wt[j * TT + i] = __expf(trans[i * TT + j] - c);
}

// ---------------------------------------------------------------------------
__global__ void __launch_bounds__(64) crf_scan_kernel(
    const float* __restrict__ feats,   // [B, S, 64]
    const float* __restrict__ masks,   // [B, S]
    float* __restrict__ out,           // [B, 64]
    int Sdim)
{
    const int b   = blockIdx.x;
    const int tid = threadIdx.x;
    const int w2  = tid >> 5;

    __shared__ alignas(16) float s_feat[3][CHUNK][TT];   // 12 KB staged feats
    __shared__ float s_mask[3][CHUNK];
    __shared__ alignas(16) float s_v[2][TT];             // warp-private halves
    __shared__ float s_part[2][TT];                      // cross-warp partials
    __shared__ float s_mring[2];                         // stale alpha[1] ring

    // W columns tid (own) and tid^32 (other), rows [32*w2, 32*w2+32),
    // loaded already-packed as u64 pairs along i.
    u64 wA[16], wB[16];
    {
        const ulonglong2* pa =
            reinterpret_cast<const ulonglong2*>(&g_Wt[tid * TT + 32 * w2]);
        const ulonglong2* pb =
            reinterpret_cast<const ulonglong2*>(&g_Wt[(tid ^ 32) * TT + 32 * w2]);
        #pragma unroll
        for (int q = 0; q < 8; q++) {
            ulonglong2 ua = pa[q];
            wA[2 * q]     = ua.x;
            wA[2 * q + 1] = ua.y;
            ulonglong2 ub = pb[q];
            wB[2 * q]     = ub.x;
            wB[2 * q + 1] = ub.y;
        }
    }
    const float cj2 = g_c2[tid];

    const float* fbp = feats + (size_t)b * Sdim * TT;
    const float* mbp = masks + (size_t)b * Sdim;
    const uint32_t feat_s0 = smem_u32(&s_feat[0][0][0]);
    const uint32_t mask_s0 = smem_u32(&s_mask[0][0]);

    const int NC = (Sdim + CHUNK - 1) / CHUNK;

    auto stage = [&](int c) {
        const int base = c * CHUNK;
        const int bufo = (c % 3) * CHUNK * TT;
        #pragma unroll
        for (int q = 0; q < 4; q++) {
            int g   = q * 64 + tid;        // 16B granule 0..255
            int row = g >> 4;
            int col = (g & 15) << 2;
            int gr  = base + row; if (gr >= Sdim) gr = Sdim - 1;
            const float* src = fbp + (size_t)gr * TT + col;
            uint32_t dst = feat_s0 + (uint32_t)(bufo + row * TT + col) * 4u;
            asm volatile("cp.async.cg.shared.global [%0], [%1], 16;" :: "r"(dst), "l"(src));
        }
        if (tid < CHUNK) {
            int gr = base + tid; if (gr >= Sdim) gr = Sdim - 1;
            const float* src = mbp + gr;
            uint32_t dst = mask_s0 + (uint32_t)((c % 3) * CHUNK + tid) * 4u;
            asm volatile("cp.async.ca.shared.global [%0], [%1], 4;" :: "r"(dst), "l"(src));
        }
    };

    stage(0);
    asm volatile("cp.async.commit_group;");
    if (NC > 1) stage(1);
    asm volatile("cp.async.commit_group;");
    asm volatile("cp.async.wait_group 1;");
    __syncthreads();

    float alpha = s_feat[0][0][tid] * L2E;   // base-2 scaled alpha0

    // Seed shift ring: slot 1 is read at t=1 (slot index = t&1 = r&1).
    if (tid == 1) s_mring[1] = alpha;
    __syncthreads();
    float m = s_mring[1];

    for (int c = 0; c < NC; c++) {
        if (c > 0) asm volatile("cp.async.wait_group 1;");
        if (c + 2 < NC) stage(c + 2);
        asm volatile("cp.async.commit_group;");
        __syncthreads();

        #pragma unroll
        for (int r = 0; r < CHUNK; r++) {
            const int t = c * CHUNK + r;
            if (t >= 1 && t < Sdim) {
                // Chain head: exp2 with stale shift, publish own v.
                const float v = ex2f(alpha - m);
                s_v[r & 1][tid] = v;

                // Publish alpha[1] for step t+1's shift (slot (t+1)&1).
                if (tid == 1) s_mring[(r & 1) ^ 1] = alpha;

                // Off-chain: staged feat/mask, blend precompute.
                const float ft  = s_feat[c % 3][r][tid];
                const float mk  = s_mask[c % 3][r];
                const float pre = fmaf(ft, L2E, cj2 + m);
                const float t0  = fmaf(mk, pre - alpha, alpha);

                __syncwarp();

                // Own-half matvec for columns tid and tid^32 (v pre-packed).
                const ulonglong2* vp =
                    reinterpret_cast<const ulonglong2*>(&s_v[r & 1][32 * w2]);
                u64 accA[4] = {0ull, 0ull, 0ull, 0ull};
                u64 accB[4] = {0ull, 0ull, 0ull, 0ull};
                #pragma unroll
                for (int q = 0; q < 8; q++) {
                    ulonglong2 u = vp[q];
                    accA[(2 * q) & 3]     = ffma2(u.x, wA[2 * q],     accA[(2 * q) & 3]);
                    accA[(2 * q + 1) & 3] = ffma2(u.y, wA[2 * q + 1], accA[(2 * q + 1) & 3]);
                    accB[(2 * q) & 3]     = ffma2(u.x, wB[2 * q],     accB[(2 * q) & 3]);
                    accB[(2 * q + 1) & 3] = ffma2(u.y, wB[2 * q + 1], accB[(2 * q + 1) & 3]);
                }
                u64 sA = fadd2(fadd2(accA[0], accA[1]), fadd2(accA[2], accA[3]));
                u64 sB = fadd2(fadd2(accB[0], accB[1]), fadd2(accB[2], accB[3]));
                float al, ah, bl, bh;
                unpack2(sA, al, ah);
                unpack2(sB, bl, bh);
                const float PA = al + ah;   // partial for OWN column tid
                const float PB = bl + bh;   // partial for column tid^32

                s_part[r & 1][tid ^ 32] = PB;

                __syncthreads();

                // Tail: combine halves, log2, blend; fetch next shift.
                const float P = PA + s_part[r & 1][tid];
                alpha = fmaf(lg2f(P), mk, t0);
                m = s_mring[(r & 1) ^ 1];
            }
        }
    }

    out[(size_t)b * TT + tid] = alpha * LN2;
}

// ---------------------------------------------------------------------------
extern "C" void kernel_launch(void* const* d_in, const int* in_sizes, int n_in,
                              void* d_out, int out_size) {
    const float* feats = (const float*)d_in[0];
    const float* masks = (const float*)d_in[1];
    const float* trans = (const float*)d_in[2];
    float* out = (float*)d_out;

    const int Bn   = out_size / TT;
    const int Sdim = in_sizes[0] / (Bn * TT);

    crf_prep_kernel<<<1, TT>>>(trans);
    crf_scan_kernel<<<Bn, TT>>>(feats, masks, out, Sdim);
}